// round 15
// baseline (speedup 1.0000x reference)
#include <cuda_runtime.h>
#include <cuda_bf16.h>
#include <cstdint>

// NCE loss (training branch, size_average=True).
// N=4096, E=1024, V=50257, K=25.
// R7-converged structure + sm_10x 256-bit global loads (LDG.E.256):
// 4 x ld.global.nc.v8.f32 per lane per dot instead of 8 x LDG.128 ->
// half the LSU issue slots / L1tex queue-accept time per dot, same bytes.
// Persistent grid 1184 CTAs (8/SM), 256 thr, x double-buffered via cp.async,
// one atomicAdd per CTA (d_out zeroed by memset node).

#define THREADS 256
#define NWARP   8
#define GRID    1184          // 148 SMs * 8 CTAs

__device__ __forceinline__ void cp16(uint32_t dst, const void* src) {
    asm volatile("cp.async.cg.shared.global [%0], [%1], 16;\n" :: "r"(dst), "l"(src));
}
__device__ __forceinline__ void cp_commit() {
    asm volatile("cp.async.commit_group;\n" ::: "memory");
}

// 256-bit non-coherent global load (sm_100+): 8 floats per instruction.
__device__ __forceinline__ void ldg256(const float* p,
                                       float& a0, float& a1, float& a2, float& a3,
                                       float& a4, float& a5, float& a6, float& a7) {
    asm volatile("ld.global.nc.v8.f32 {%0,%1,%2,%3,%4,%5,%6,%7}, [%8];"
                 : "=f"(a0), "=f"(a1), "=f"(a2), "=f"(a3),
                   "=f"(a4), "=f"(a5), "=f"(a6), "=f"(a7)
                 : "l"(p));
}

__global__ __launch_bounds__(THREADS, 8)
void nce_main(const float* __restrict__ x,
              const int*   __restrict__ target,
              const int*   __restrict__ noise_idx,
              const float* __restrict__ weight,
              const float* __restrict__ bias,
              const float* __restrict__ noise,
              float* __restrict__ out,
              int N, int E, int K)
{
    const int tid  = threadIdx.x;
    const int lane = tid & 31;
    const int wid  = tid >> 5;
    const int nk   = K + 1;                // 26

    __shared__ float4 xs[2][256];          // double-buffered x row (as floats below)
    __shared__ float  wloss[NWARP];

    uint32_t xs_addr[2];
    {
        uint32_t base;
        asm("{ .reg .u64 t; cvta.to.shared.u64 t, %1; cvt.u32.u64 %0, t; }"
            : "=r"(base) : "l"(&xs[0][0]));
        xs_addr[0] = base + tid * 16;
        xs_addr[1] = base + 4096 + tid * 16;
    }

    // Prime buffer 0 with the first row's x
    const int n0 = blockIdx.x;
    if (n0 < N) {
        cp16(xs_addr[0], (const char*)(x + (size_t)n0 * E) + tid * 16);
        cp_commit();
    }

    float loss = 0.0f;                     // lane-0-held across rows
    int buf = 0;

    for (int n = n0; n < N; n += GRID, buf ^= 1) {
        const int n_next = n + GRID;
        if (n_next < N) {
            cp16(xs_addr[buf ^ 1], (const char*)(x + (size_t)n_next * E) + tid * 16);
            cp_commit();
            asm volatile("cp.async.wait_group 1;\n" ::: "memory");
        } else {
            asm volatile("cp.async.wait_group 0;\n" ::: "memory");
        }
        __syncthreads();

        const float* xf = reinterpret_cast<const float*>(xs[buf]);

        for (int k = wid; k < nk; k += NWARP) {
            const int idx = (k == 0) ? target[n] : noise_idx[n * K + (k - 1)];
            const float* wrow = weight + (size_t)idx * E;

            // lane's 32B chunks: float offsets j*256 + lane*8, j = 0..3
            float s = 0.0f;
            #pragma unroll
            for (int j = 0; j < 4; j++) {   // 4 independent LDG.256 per lane
                const int o = j * 256 + lane * 8;
                float w0, w1, w2, w3, w4, w5, w6, w7;
                ldg256(wrow + o, w0, w1, w2, w3, w4, w5, w6, w7);
                const float4 xa = *reinterpret_cast<const float4*>(xf + o);
                const float4 xb = *reinterpret_cast<const float4*>(xf + o + 4);
                s += w0 * xa.x + w1 * xa.y + w2 * xa.z + w3 * xa.w;
                s += w4 * xb.x + w5 * xb.y + w6 * xb.z + w7 * xb.w;
            }
            #pragma unroll
            for (int o = 16; o; o >>= 1)
                s += __shfl_xor_sync(0xffffffffu, s, o);

            if (lane == 0) {
                const float logit = s + __ldg(&bias[idx]);
                const float p     = __expf(logit - 9.0f);
                const float kpn   = 25.0f * __ldg(&noise[idx]);
                const float num   = (k == 0) ? p : kpn;
                loss += __logf(num / (p + kpn));
            }
        }
        __syncthreads();   // xs[buf] fully consumed before refill
    }

    if (lane == 0) wloss[wid] = loss;
    __syncthreads();
    if (tid == 0) {
        float t = 0.0f;
        #pragma unroll
        for (int w = 0; w < NWARP; w++) t += wloss[w];
        atomicAdd(out, -t / (float)N);     // one atomic per CTA
    }
}

extern "C" void kernel_launch(void* const* d_in, const int* in_sizes, int n_in,
                              void* d_out, int out_size)
{
    const float* x         = (const float*)d_in[0];
    const int*   target    = (const int*)  d_in[1];
    const int*   noise_idx = (const int*)  d_in[2];
    const float* weight    = (const float*)d_in[3];
    const float* bias      = (const float*)d_in[4];
    const float* noise     = (const float*)d_in[5];

    const int N = in_sizes[1];            // 4096
    const int E = in_sizes[0] / N;        // 1024
    const int K = in_sizes[2] / N;        // 25

    cudaMemsetAsync(d_out, 0, sizeof(float));
    nce_main<<<GRID, THREADS>>>(x, target, noise_idx, weight, bias, noise,
                                (float*)d_out, N, E, K);
}

// round 16
// speedup vs baseline: 1.1208x; 1.1208x over previous
#include <cuda_runtime.h>
#include <cuda_bf16.h>
#include <cstdint>

// NCE loss (training branch, size_average=True).  FINAL KERNEL (R7 config,
// fastest of 15 measured variants: 57.4us).
// N=4096, E=1024, V=50257, K=25.
//
// Binding constraint (established over 15 benches): the irreducible ~436MB
// random fp32 weight-row gather (4096 rows x 26 candidates x 4KB) through
// L1tex/LTS. Occupancy 36-90%, MLP 2-8, LDG.128 vs LDG.256, DRAM bytes
// 231-302MB (two-pass L2 blocking), 0-2 barriers/row, cp.async weight
// staging, warp-autonomous flattening, three epilogue styles -- all land at
// 57-66us with this config at the bottom. Gather-equilibrium floor ~57us.
//
// Design: persistent grid of 1184 CTAs (8/SM x 148 SMs = 64 warps/SM, HW max),
// 256 thr / 32 regs. Each CTA grid-strides rows; per row, 8 warps cover the
// 26 dot products (8 independent LDG.128 per lane + warp-shfl reduce). x rows
// are double-buffered in SMEM via cp.async so the next row's x streams behind
// the current row's dots. Epilogue: one float atomicAdd per CTA into d_out
// (zeroed each replay by a 4-byte memset node).

#define THREADS 256
#define NWARP   8
#define GRID    1184          // 148 SMs * 8 CTAs

__device__ __forceinline__ void cp16(uint32_t dst, const void* src) {
    asm volatile("cp.async.cg.shared.global [%0], [%1], 16;\n" :: "r"(dst), "l"(src));
}
__device__ __forceinline__ void cp_commit() {
    asm volatile("cp.async.commit_group;\n" ::: "memory");
}

__global__ __launch_bounds__(THREADS, 8)
void nce_main(const float* __restrict__ x,
              const int*   __restrict__ target,
              const int*   __restrict__ noise_idx,
              const float* __restrict__ weight,
              const float* __restrict__ bias,
              const float* __restrict__ noise,
              float* __restrict__ out,
              int N, int E, int K)
{
    const int tid  = threadIdx.x;
    const int lane = tid & 31;
    const int wid  = tid >> 5;
    const int nk   = K + 1;                // 26

    __shared__ float4 xs[2][256];          // double-buffered x row
    __shared__ float  wloss[NWARP];

    uint32_t xs_addr[2];
    {
        uint32_t base;
        asm("{ .reg .u64 t; cvta.to.shared.u64 t, %1; cvt.u32.u64 %0, t; }"
            : "=r"(base) : "l"(&xs[0][0]));
        xs_addr[0] = base + tid * 16;
        xs_addr[1] = base + 4096 + tid * 16;
    }

    // Prime buffer 0 with the first row's x
    const int n0 = blockIdx.x;
    if (n0 < N) {
        cp16(xs_addr[0], (const char*)(x + (size_t)n0 * E) + tid * 16);
        cp_commit();
    }

    float loss = 0.0f;                     // lane-0-held across rows
    int buf = 0;

    for (int n = n0; n < N; n += GRID, buf ^= 1) {
        // Start streaming the NEXT row's x into the other buffer
        const int n_next = n + GRID;
        if (n_next < N) {
            cp16(xs_addr[buf ^ 1], (const char*)(x + (size_t)n_next * E) + tid * 16);
            cp_commit();
            asm volatile("cp.async.wait_group 1;\n" ::: "memory");  // this row in
        } else {
            asm volatile("cp.async.wait_group 0;\n" ::: "memory");
        }
        __syncthreads();

        const float4* xb = xs[buf];

        for (int k = wid; k < nk; k += NWARP) {
            const int idx = (k == 0) ? target[n] : noise_idx[n * K + (k - 1)];
            const float4* wrow = reinterpret_cast<const float4*>(weight + (size_t)idx * E);

            float s = 0.0f;
            #pragma unroll
            for (int j = 0; j < 8; j++) {   // 8 independent LDG.128 per lane
                const float4 wv = __ldg(&wrow[lane + 32 * j]);
                const float4 xv = xb[lane + 32 * j];
                s += wv.x * xv.x + wv.y * xv.y + wv.z * xv.z + wv.w * xv.w;
            }
            #pragma unroll
            for (int o = 16; o; o >>= 1)
                s += __shfl_xor_sync(0xffffffffu, s, o);

            if (lane == 0) {
                const float logit = s + __ldg(&bias[idx]);
                const float p     = __expf(logit - 9.0f);
                const float kpn   = 25.0f * __ldg(&noise[idx]);
                const float num   = (k == 0) ? p : kpn;
                loss += __logf(num / (p + kpn));
            }
        }
        __syncthreads();   // xs[buf] fully consumed before refill
    }

    if (lane == 0) wloss[wid] = loss;
    __syncthreads();
    if (tid == 0) {
        float t = 0.0f;
        #pragma unroll
        for (int w = 0; w < NWARP; w++) t += wloss[w];
        atomicAdd(out, -t / (float)N);     // one atomic per CTA
    }
}

extern "C" void kernel_launch(void* const* d_in, const int* in_sizes, int n_in,
                              void* d_out, int out_size)
{
    const float* x         = (const float*)d_in[0];
    const int*   target    = (const int*)  d_in[1];
    const int*   noise_idx = (const int*)  d_in[2];
    const float* weight    = (const float*)d_in[3];
    const float* bias      = (const float*)d_in[4];
    const float* noise     = (const float*)d_in[5];

    const int N = in_sizes[1];            // 4096
    const int E = in_sizes[0] / N;        // 1024
    const int K = in_sizes[2] / N;        // 25

    cudaMemsetAsync(d_out, 0, sizeof(float));
    nce_main<<<GRID, THREADS>>>(x, target, noise_idx, weight, bias, noise,
                                (float*)d_out, N, E, K);
}